// round 10
// baseline (speedup 1.0000x reference)
#include <cuda_runtime.h>

// Two-kernel fused spiking conv2d (T=128, Cin=16, Cout=64, 64x64, pad=1) + LIF.
// K1: conv+bias. Thread = 4 adjacent pixels x 8 couts (32 outputs).
//     DUAL-PARITY smem: xs (aligned copy) + xsh (1-float-shifted copy) so all
//     five f32x2 operand pairs load as naturally aligned register pairs:
//     zero pack-MOVs, zero shuffles, zero edge predicates in the inner loop
//     (R8/R9 showed alu% == fma%: packs/shuffles were half the work).
// K2: in-place float4 LIF scan (DRAM-bound, near floor).
// Bit-exact: per-output (cin,kh,kw) fma2 chain + (conv+b) then (state+conv).

#define T_STEPS 128
#define CIN     16
#define HH      64
#define WWID    64
#define COUT    64

#define BAND    8               // output rows per block
#define ROWS_S  10              // band + top/bottom halo rows
#define COLS_P  68              // padded row stride (floats), 272B = 17*16B
#define NROWS   (CIN * ROWS_S)  // 160 staged rows
#define XS_FLOATS (NROWS * COLS_P)   // 10880 floats per buffer

typedef unsigned long long ull;

__device__ __forceinline__ void fma2(ull& d, ull a, ull b) {
    asm("fma.rn.f32x2 %0, %1, %2, %0;" : "+l"(d) : "l"(a), "l"(b));
}
__device__ __forceinline__ void unpack2(ull v, float& lo, float& hi) {
    asm("mov.b64 {%0, %1}, %2;" : "=f"(lo), "=f"(hi) : "l"(v));
}
__device__ __forceinline__ float fadd(float a, float b) {
    float r;
    asm("add.rn.f32 %0, %1, %2;" : "=f"(r) : "f"(a), "f"(b));
    return r;
}
__device__ __forceinline__ void cp16(unsigned saddr, const void* g) {
    asm volatile("cp.async.cg.shared.global [%0], [%1], 16;"
                 :: "r"(saddr), "l"(g));
}
__device__ __forceinline__ void cp_commit() {
    asm volatile("cp.async.commit_group;");
}
__device__ __forceinline__ void cp_wait0() {
    asm volatile("cp.async.wait_group 0;");
}

// ---------------- K1: conv + bias ------------------------------------------
// Block: 128 threads = 8 ty (band rows) x 16 tx (w-quads).
// Grid: (8 row-bands, 8 cout-groups, 32 timesteps) x 4 launches.
__global__ __launch_bounds__(128)
void conv_kernel(const float* __restrict__ x,
                 const float* __restrict__ Wg,
                 const float* __restrict__ bg,
                 float* __restrict__ out,
                 int t0)
{
    extern __shared__ float xs[];                 // [NROWS][COLS_P] aligned copy
    float* xsh = xs + XS_FLOATS;                  // [NROWS][COLS_P] shifted copy
    __shared__ float2 ws[CIN][9][8];              // duplicated weight pairs

    const int tid = threadIdx.x;
    const int ty  = tid >> 4;            // 0..7  : row within band
    const int tx  = tid & 15;            // 0..15 : w-quad
    const int ht  = blockIdx.x * BAND;   // band start row
    const int c0  = blockIdx.y << 3;     // cout group of 8
    const int t   = t0 + blockIdx.z;     // timestep

    const int h0 = ht + ty;
    const int w0 = tx * 4;

    const float* xsrc = x + (size_t)t * (CIN * HH * WWID);

    unsigned xs_u32;
    {
        unsigned long long tmp = __cvta_generic_to_shared(xs);
        xs_u32 = (unsigned)tmp;
    }

    // ---- stage xs: aligned copy via cp.async; zero invalid halo rows ----
    for (int rowid = tid; rowid < NROWS; rowid += 128) {
        int cin = rowid / ROWS_S;
        int rr  = rowid - cin * ROWS_S;
        int gh  = ht - 1 + rr;
        unsigned sdst = xs_u32 + (unsigned)(rowid * COLS_P * 4);
        if (gh >= 0 && gh < HH) {
            const char* g = (const char*)(xsrc + cin * (HH * WWID) + gh * WWID);
            #pragma unroll
            for (int k = 0; k < 16; ++k)
                cp16(sdst + k * 16, g + k * 16);
        } else {
            float4* z = reinterpret_cast<float4*>(xs + rowid * COLS_P);
            #pragma unroll
            for (int k = 0; k < 16; ++k)
                z[k] = make_float4(0.f, 0.f, 0.f, 0.f);
        }
    }
    cp_commit();

    // ---- stage xsh: shifted copy (xsh[c] = x[c-1]) via predicated LDG,
    //      overlapping the cp.async traffic above ----
    for (int cid = tid; cid < NROWS * 17; cid += 128) {
        int row = cid / 17;
        int m   = cid - row * 17;
        int cin = row / ROWS_S;
        int rr  = row - cin * ROWS_S;
        int gh  = ht - 1 + rr;
        bool ghv = (gh >= 0) && (gh < HH);
        const float* g = xsrc + cin * (HH * WWID) + gh * WWID;
        float v0 = 0.f, v1 = 0.f, v2 = 0.f, v3 = 0.f;
        int cg = 4 * m - 1;
        if (ghv) {
            if ((unsigned)(cg + 0) < 64u) v0 = __ldg(g + cg + 0);
            if ((unsigned)(cg + 1) < 64u) v1 = __ldg(g + cg + 1);
            if ((unsigned)(cg + 2) < 64u) v2 = __ldg(g + cg + 2);
            if ((unsigned)(cg + 3) < 64u) v3 = __ldg(g + cg + 3);
        }
        *reinterpret_cast<float4*>(xsh + row * COLS_P + 4 * m) =
            make_float4(v0, v1, v2, v3);
    }

    // ---- stage duplicated weight pairs: 16*9*8 = 1152 entries ----
    for (int i = tid; i < CIN * 9 * 8; i += 128) {
        int c   = i & 7;
        int rem = i >> 3;
        int tap = rem % 9;
        int cin = rem / 9;
        float w = Wg[((c0 + c) * CIN + cin) * 9 + tap];
        ws[cin][tap][c] = make_float2(w, w);
    }

    cp_wait0();
    __syncthreads();

    // accumulators: a[c] = pixpair (p0,p1), b[c] = pixpair (p2,p3)
    ull a[8], b[8];
    #pragma unroll
    for (int c = 0; c < 8; ++c) { a[c] = 0ull; b[c] = 0ull; }

    #pragma unroll 4
    for (int cin = 0; cin < CIN; ++cin) {
        #pragma unroll
        for (int r = 0; r < 3; ++r) {
            const int rowoff = (cin * ROWS_S + ty + r) * COLS_P + w0;
            // all operand pairs naturally aligned -- no packs, no shuffles
            ulonglong2 xv = *reinterpret_cast<const ulonglong2*>(xs  + rowoff);
            ulonglong2 sv = *reinterpret_cast<const ulonglong2*>(xsh + rowoff);
            ull q4 = *reinterpret_cast<const ull*>(xsh + rowoff + 4);
            // q0 = sv.x = (x[-1],x0)   kw0 for pixpair0
            // q1 = xv.x = (x0,x1)      kw1 pp0
            // q2 = sv.y = (x1,x2)      kw2 pp0 / kw0 pp1
            // q3 = xv.y = (x2,x3)      kw1 pp1
            // q4 =        (x3,x4)      kw2 pp1

            const ulonglong2* w0v =
                reinterpret_cast<const ulonglong2*>(&ws[cin][r * 3 + 0][0]);
            const ulonglong2* w1v =
                reinterpret_cast<const ulonglong2*>(&ws[cin][r * 3 + 1][0]);
            const ulonglong2* w2v =
                reinterpret_cast<const ulonglong2*>(&ws[cin][r * 3 + 2][0]);

            #pragma unroll
            for (int j = 0; j < 4; ++j) {
                ulonglong2 W0 = w0v[j];   // kw=0, couts 2j, 2j+1
                ulonglong2 W1 = w1v[j];   // kw=1
                ulonglong2 W2 = w2v[j];   // kw=2
                // per-accumulator order: kw0, kw1, kw2 (bit-exact chain)
                fma2(a[2*j],   sv.x, W0.x);  fma2(a[2*j+1], sv.x, W0.y);
                fma2(b[2*j],   sv.y, W0.x);  fma2(b[2*j+1], sv.y, W0.y);
                fma2(a[2*j],   xv.x, W1.x);  fma2(a[2*j+1], xv.x, W1.y);
                fma2(b[2*j],   xv.y, W1.x);  fma2(b[2*j+1], xv.y, W1.y);
                fma2(a[2*j],   sv.y, W2.x);  fma2(a[2*j+1], sv.y, W2.y);
                fma2(b[2*j],   q4,   W2.x);  fma2(b[2*j+1], q4,   W2.y);
            }
        }
    }

    // ---- write rounded conv_t + b as float4 per cout ----
    float* o = out + (size_t)t * (COUT * HH * WWID)
                   + (size_t)c0 * (HH * WWID) + h0 * WWID + w0;
    #pragma unroll
    for (int c = 0; c < 8; ++c) {
        const float bb = bg[c0 + c];
        float p0, p1, p2, p3;
        unpack2(a[c], p0, p1);
        unpack2(b[c], p2, p3);
        *reinterpret_cast<float4*>(o + (size_t)c * (HH * WWID)) =
            make_float4(fadd(p0, bb), fadd(p1, bb), fadd(p2, bb), fadd(p3, bb));
    }
}

// ---------------- K2: in-place LIF scan over t (float4) ---------------------
__global__ __launch_bounds__(256)
void scan_kernel(float* __restrict__ out)
{
    const int idx = blockIdx.x * 256 + threadIdx.x;   // float4 element index
    float4* p = reinterpret_cast<float4*>(out) + idx;
    const int stride4 = (COUT * HH * WWID) / 4;

    float4 s = make_float4(0.f, 0.f, 0.f, 0.f);
    #pragma unroll 4
    for (int t = 0; t < T_STEPS; ++t) {
        float4 c = p[(size_t)t * stride4];
        float4 v;
        v.x = fadd(s.x, c.x); v.y = fadd(s.y, c.y);
        v.z = fadd(s.z, c.z); v.w = fadd(s.w, c.w);
        float4 k;
        k.x = (v.x >= 8.f) ? 1.f : 0.f;  k.y = (v.y >= 8.f) ? 1.f : 0.f;
        k.z = (v.z >= 8.f) ? 1.f : 0.f;  k.w = (v.w >= 8.f) ? 1.f : 0.f;
        v.x = (v.x >= 8.f) ? 0.f : v.x;  v.y = (v.y >= 8.f) ? 0.f : v.y;
        v.z = (v.z >= 8.f) ? 0.f : v.z;  v.w = (v.w >= 8.f) ? 0.f : v.w;
        s.x = fmaxf(v.x, -1.f);          s.y = fmaxf(v.y, -1.f);
        s.z = fmaxf(v.z, -1.f);          s.w = fmaxf(v.w, -1.f);
        p[(size_t)t * stride4] = k;
    }
}

extern "C" void kernel_launch(void* const* d_in, const int* in_sizes, int n_in,
                              void* d_out, int out_size)
{
    const float* x  = (const float*)d_in[0];   // [128,16,64,64]
    const float* Wg = (const float*)d_in[1];   // [64,16,3,3]
    const float* bg = (const float*)d_in[2];   // [64]
    float* out      = (float*)d_out;           // [128,64,64,64]

    static int attr_set = 0;
    size_t xs_bytes = (size_t)2 * XS_FLOATS * sizeof(float);   // 87040 B
    if (!attr_set) {
        cudaFuncSetAttribute(conv_kernel,
                             cudaFuncAttributeMaxDynamicSharedMemorySize,
                             (int)xs_bytes);
        attr_set = 1;
    }

    // 4 t-chunk launches: keeps ncu's sampled launch (#6 overall) on conv.
    dim3 grid1(8, 8, 32);   // 8 row bands x 8 cout groups x 32 timesteps
    conv_kernel<<<grid1, 128, xs_bytes>>>(x, Wg, bg, out, 0);
    conv_kernel<<<grid1, 128, xs_bytes>>>(x, Wg, bg, out, 32);
    conv_kernel<<<grid1, 128, xs_bytes>>>(x, Wg, bg, out, 64);
    conv_kernel<<<grid1, 128, xs_bytes>>>(x, Wg, bg, out, 96);

    scan_kernel<<<(COUT * HH * WWID) / 4 / 256, 256>>>(out);
}

// round 11
// speedup vs baseline: 1.4698x; 1.4698x over previous
#include <cuda_runtime.h>

// Two-kernel fused spiking conv2d (T=128, Cin=16, Cout=64, 64x64, pad=1) + LIF.
// K1: conv+bias. 256-thread block = TWO cout-groups of 8 sharing one x tile:
//     half-block cg handles couts [c0+8cg, c0+8cg+8) over an 8-row band.
//     DUAL-PARITY smem (aligned xs + 1-float-shifted xsh) -> all f32x2 operand
//     pairs are naturally register-aligned: no packs/shuffles (R10: alu 9.6%).
//     Sharing the tile doubles resident warps/SMSP (R10's failure: occ 12%).
// K2: in-place float4 LIF scan (DRAM-bound, near floor).
// Bit-exact: per-output (cin,kh,kw) fma2 chain + (conv+b) then (state+conv).

#define T_STEPS 128
#define CIN     16
#define HH      64
#define WWID    64
#define COUT    64

#define BAND    8               // output rows per block
#define ROWS_S  10              // band + top/bottom halo rows
#define COLS_P  68              // padded row stride (floats), 272B
#define NROWS   (CIN * ROWS_S)  // 160 staged rows
#define XS_FLOATS (NROWS * COLS_P)   // 10880 floats per buffer

typedef unsigned long long ull;

__device__ __forceinline__ void fma2(ull& d, ull a, ull b) {
    asm("fma.rn.f32x2 %0, %1, %2, %0;" : "+l"(d) : "l"(a), "l"(b));
}
__device__ __forceinline__ void unpack2(ull v, float& lo, float& hi) {
    asm("mov.b64 {%0, %1}, %2;" : "=f"(lo), "=f"(hi) : "l"(v));
}
__device__ __forceinline__ float fadd(float a, float b) {
    float r;
    asm("add.rn.f32 %0, %1, %2;" : "=f"(r) : "f"(a), "f"(b));
    return r;
}
__device__ __forceinline__ void cp16(unsigned saddr, const void* g) {
    asm volatile("cp.async.cg.shared.global [%0], [%1], 16;"
                 :: "r"(saddr), "l"(g));
}
__device__ __forceinline__ void cp_commit() {
    asm volatile("cp.async.commit_group;");
}
__device__ __forceinline__ void cp_wait0() {
    asm volatile("cp.async.wait_group 0;");
}

// ---------------- K1: conv + bias ------------------------------------------
// Block: 256 threads = 2 cout-halves x (8 ty rows x 16 tx quads).
// Grid: (8 row-bands, 4 cout-pairs, 32 timesteps) x 4 launches.
__global__ __launch_bounds__(256, 2)
void conv_kernel(const float* __restrict__ x,
                 const float* __restrict__ Wg,
                 const float* __restrict__ bg,
                 float* __restrict__ out,
                 int t0)
{
    extern __shared__ float xs[];                 // [NROWS][COLS_P] aligned
    float* xsh = xs + XS_FLOATS;                  // [NROWS][COLS_P] shifted
    __shared__ float2 ws[CIN][9][16];             // weight pairs, 16 couts

    const int tid = threadIdx.x;
    const int cg  = tid >> 7;            // 0/1 : cout half
    const int rt  = tid & 127;
    const int ty  = rt >> 4;             // 0..7  : row within band
    const int tx  = rt & 15;             // 0..15 : w-quad
    const int ht  = blockIdx.x * BAND;   // band start row
    const int c0  = (blockIdx.y << 4) + (cg << 3);   // this half's cout base
    const int t   = t0 + blockIdx.z;     // timestep

    const int h0 = ht + ty;
    const int w0 = tx * 4;

    const float* xsrc = x + (size_t)t * (CIN * HH * WWID);

    unsigned xs_u32;
    {
        unsigned long long tmp = __cvta_generic_to_shared(xs);
        xs_u32 = (unsigned)tmp;
    }

    // ---- stage xs: aligned copy via cp.async; zero invalid halo rows ----
    for (int rowid = tid; rowid < NROWS; rowid += 256) {
        int cin = rowid / ROWS_S;
        int rr  = rowid - cin * ROWS_S;
        int gh  = ht - 1 + rr;
        unsigned sdst = xs_u32 + (unsigned)(rowid * COLS_P * 4);
        if (gh >= 0 && gh < HH) {
            const char* g = (const char*)(xsrc + cin * (HH * WWID) + gh * WWID);
            #pragma unroll
            for (int k = 0; k < 16; ++k)
                cp16(sdst + k * 16, g + k * 16);
        } else {
            float4* z = reinterpret_cast<float4*>(xs + rowid * COLS_P);
            #pragma unroll
            for (int k = 0; k < 16; ++k)
                z[k] = make_float4(0.f, 0.f, 0.f, 0.f);
        }
    }
    cp_commit();

    // ---- stage xsh: shifted copy (xsh[c] = x[c-1]) via predicated LDG ----
    for (int cid = tid; cid < NROWS * 17; cid += 256) {
        int row = cid / 17;
        int m   = cid - row * 17;
        int cin = row / ROWS_S;
        int rr  = row - cin * ROWS_S;
        int gh  = ht - 1 + rr;
        bool ghv = (gh >= 0) && (gh < HH);
        const float* g = xsrc + cin * (HH * WWID) + gh * WWID;
        float v0 = 0.f, v1 = 0.f, v2 = 0.f, v3 = 0.f;
        int cgx = 4 * m - 1;
        if (ghv) {
            if ((unsigned)(cgx + 0) < 64u) v0 = __ldg(g + cgx + 0);
            if ((unsigned)(cgx + 1) < 64u) v1 = __ldg(g + cgx + 1);
            if ((unsigned)(cgx + 2) < 64u) v2 = __ldg(g + cgx + 2);
            if ((unsigned)(cgx + 3) < 64u) v3 = __ldg(g + cgx + 3);
        }
        *reinterpret_cast<float4*>(xsh + row * COLS_P + 4 * m) =
            make_float4(v0, v1, v2, v3);
    }

    // ---- stage duplicated weight pairs: 16*9*16 = 2304 entries ----
    {
        const int cbase = blockIdx.y << 4;
        for (int i = tid; i < CIN * 9 * 16; i += 256) {
            int c   = i & 15;
            int rem = i >> 4;
            int tap = rem % 9;
            int cin = rem / 9;
            float w = Wg[((cbase + c) * CIN + cin) * 9 + tap];
            ws[cin][tap][c] = make_float2(w, w);
        }
    }

    cp_wait0();
    __syncthreads();

    // accumulators: a[c] = pixpair (p0,p1), b[c] = pixpair (p2,p3)
    ull a[8], b[8];
    #pragma unroll
    for (int c = 0; c < 8; ++c) { a[c] = 0ull; b[c] = 0ull; }

    const int cg8 = cg << 3;

    #pragma unroll 4
    for (int cin = 0; cin < CIN; ++cin) {
        #pragma unroll
        for (int r = 0; r < 3; ++r) {
            const int rowoff = (cin * ROWS_S + ty + r) * COLS_P + w0;
            // all operand pairs naturally aligned -- no packs, no shuffles
            ulonglong2 xv = *reinterpret_cast<const ulonglong2*>(xs  + rowoff);
            ulonglong2 sv = *reinterpret_cast<const ulonglong2*>(xsh + rowoff);
            ull q4 = *reinterpret_cast<const ull*>(xsh + rowoff + 4);
            // sv.x = (x-1,x0) kw0 pp0 ; xv.x = (x0,x1) kw1 pp0
            // sv.y = (x1,x2)  kw2 pp0 / kw0 pp1 ; xv.y = (x2,x3) kw1 pp1
            // q4   = (x3,x4)  kw2 pp1

            const ulonglong2* w0v =
                reinterpret_cast<const ulonglong2*>(&ws[cin][r * 3 + 0][cg8]);
            const ulonglong2* w1v =
                reinterpret_cast<const ulonglong2*>(&ws[cin][r * 3 + 1][cg8]);
            const ulonglong2* w2v =
                reinterpret_cast<const ulonglong2*>(&ws[cin][r * 3 + 2][cg8]);

            #pragma unroll
            for (int j = 0; j < 4; ++j) {
                ulonglong2 W0 = w0v[j];   // kw=0, couts 2j, 2j+1
                ulonglong2 W1 = w1v[j];   // kw=1
                ulonglong2 W2 = w2v[j];   // kw=2
                // per-accumulator order: kw0, kw1, kw2 (bit-exact chain)
                fma2(a[2*j],   sv.x, W0.x);  fma2(a[2*j+1], sv.x, W0.y);
                fma2(b[2*j],   sv.y, W0.x);  fma2(b[2*j+1], sv.y, W0.y);
                fma2(a[2*j],   xv.x, W1.x);  fma2(a[2*j+1], xv.x, W1.y);
                fma2(b[2*j],   xv.y, W1.x);  fma2(b[2*j+1], xv.y, W1.y);
                fma2(a[2*j],   sv.y, W2.x);  fma2(a[2*j+1], sv.y, W2.y);
                fma2(b[2*j],   q4,   W2.x);  fma2(b[2*j+1], q4,   W2.y);
            }
        }
    }

    // ---- write rounded conv_t + b as float4 per cout ----
    float* o = out + (size_t)t * (COUT * HH * WWID)
                   + (size_t)c0 * (HH * WWID) + h0 * WWID + w0;
    #pragma unroll
    for (int c = 0; c < 8; ++c) {
        const float bb = bg[c0 + c];
        float p0, p1, p2, p3;
        unpack2(a[c], p0, p1);
        unpack2(b[c], p2, p3);
        *reinterpret_cast<float4*>(o + (size_t)c * (HH * WWID)) =
            make_float4(fadd(p0, bb), fadd(p1, bb), fadd(p2, bb), fadd(p3, bb));
    }
}

// ---------------- K2: in-place LIF scan over t (float4) ---------------------
__global__ __launch_bounds__(256)
void scan_kernel(float* __restrict__ out)
{
    const int idx = blockIdx.x * 256 + threadIdx.x;   // float4 element index
    float4* p = reinterpret_cast<float4*>(out) + idx;
    const int stride4 = (COUT * HH * WWID) / 4;

    float4 s = make_float4(0.f, 0.f, 0.f, 0.f);
    #pragma unroll 4
    for (int t = 0; t < T_STEPS; ++t) {
        float4 c = p[(size_t)t * stride4];
        float4 v;
        v.x = fadd(s.x, c.x); v.y = fadd(s.y, c.y);
        v.z = fadd(s.z, c.z); v.w = fadd(s.w, c.w);
        float4 k;
        k.x = (v.x >= 8.f) ? 1.f : 0.f;  k.y = (v.y >= 8.f) ? 1.f : 0.f;
        k.z = (v.z >= 8.f) ? 1.f : 0.f;  k.w = (v.w >= 8.f) ? 1.f : 0.f;
        v.x = (v.x >= 8.f) ? 0.f : v.x;  v.y = (v.y >= 8.f) ? 0.f : v.y;
        v.z = (v.z >= 8.f) ? 0.f : v.z;  v.w = (v.w >= 8.f) ? 0.f : v.w;
        s.x = fmaxf(v.x, -1.f);          s.y = fmaxf(v.y, -1.f);
        s.z = fmaxf(v.z, -1.f);          s.w = fmaxf(v.w, -1.f);
        p[(size_t)t * stride4] = k;
    }
}

extern "C" void kernel_launch(void* const* d_in, const int* in_sizes, int n_in,
                              void* d_out, int out_size)
{
    const float* x  = (const float*)d_in[0];   // [128,16,64,64]
    const float* Wg = (const float*)d_in[1];   // [64,16,3,3]
    const float* bg = (const float*)d_in[2];   // [64]
    float* out      = (float*)d_out;           // [128,64,64,64]

    static int attr_set = 0;
    size_t xs_bytes = (size_t)2 * XS_FLOATS * sizeof(float);   // 87040 B
    if (!attr_set) {
        cudaFuncSetAttribute(conv_kernel,
                             cudaFuncAttributeMaxDynamicSharedMemorySize,
                             (int)xs_bytes);
        attr_set = 1;
    }

    // 4 t-chunk launches: keeps ncu's sampled launch (#6 overall) on conv.
    dim3 grid1(8, 4, 32);   // 8 row bands x 4 cout-pairs x 32 timesteps
    conv_kernel<<<grid1, 256, xs_bytes>>>(x, Wg, bg, out, 0);
    conv_kernel<<<grid1, 256, xs_bytes>>>(x, Wg, bg, out, 32);
    conv_kernel<<<grid1, 256, xs_bytes>>>(x, Wg, bg, out, 64);
    conv_kernel<<<grid1, 256, xs_bytes>>>(x, Wg, bg, out, 96);

    scan_kernel<<<(COUT * HH * WWID) / 4 / 256, 256>>>(out);
}

// round 12
// speedup vs baseline: 1.9258x; 1.3102x over previous
#include <cuda_runtime.h>

// Two-kernel fused spiking conv2d (T=128, Cin=16, Cout=64, 64x64, pad=1) + LIF.
// K1: conv+bias. f32x2 lanes = COUT-PAIRS (not pixel pairs):
//     - weight pairs load non-duplicated from smem float[16] rows (6 LDS.128
//       broadcasts/iter vs 12 duplicated ones -> halves weight wavefronts);
//     - x enters as (x,x) dup pairs made by cheap ALU MOVs (ALU was at 9%);
//     - no parity problem -> single x buffer with in-smem column halos,
//       xsh buffer + its LDG/STS staging deleted; smem 55KB -> 3 blocks/SM.
// K2: in-place float4 LIF scan (DRAM-bound, near floor).
// Bit-exact: per-output (cin,kh,kw) fma2 chain + (conv+b) then (state+conv).

#define T_STEPS 128
#define CIN     16
#define HH      64
#define WWID    64
#define COUT    64

#define BAND    8               // output rows per block
#define ROWS_S  10              // band + top/bottom halo rows
#define COLS_P  72              // 4 left-pad + 64 + 4 right-pad (16B aligned)
#define XOFF    4               // column c stored at [XOFF + c]
#define NROWS   (CIN * ROWS_S)  // 160 staged rows
#define XS_FLOATS (NROWS * COLS_P)   // 11520 floats = 46080 B

typedef unsigned long long ull;

__device__ __forceinline__ void fma2(ull& d, ull a, ull b) {
    asm("fma.rn.f32x2 %0, %1, %2, %0;" : "+l"(d) : "l"(a), "l"(b));
}
__device__ __forceinline__ ull dup2(float v) {
    ull r;
    asm("mov.b64 %0, {%1, %1};" : "=l"(r) : "f"(v));
    return r;
}
__device__ __forceinline__ void unpack2(ull v, float& lo, float& hi) {
    asm("mov.b64 {%0, %1}, %2;" : "=f"(lo), "=f"(hi) : "l"(v));
}
__device__ __forceinline__ float fadd(float a, float b) {
    float r;
    asm("add.rn.f32 %0, %1, %2;" : "=f"(r) : "f"(a), "f"(b));
    return r;
}
__device__ __forceinline__ void cp16(unsigned saddr, const void* g) {
    asm volatile("cp.async.cg.shared.global [%0], [%1], 16;"
                 :: "r"(saddr), "l"(g));
}
__device__ __forceinline__ void cp_commit() {
    asm volatile("cp.async.commit_group;");
}
__device__ __forceinline__ void cp_wait0() {
    asm volatile("cp.async.wait_group 0;");
}

// ---------------- K1: conv + bias ------------------------------------------
// Block: 256 threads = 2 cout-halves x (8 ty rows x 16 tx quads).
// Grid: (8 row-bands, 4 cout-pairs, 32 timesteps) x 4 launches.
__global__ __launch_bounds__(256, 3)
void conv_kernel(const float* __restrict__ x,
                 const float* __restrict__ Wg,
                 const float* __restrict__ bg,
                 float* __restrict__ out,
                 int t0)
{
    extern __shared__ float xs[];                 // [NROWS][COLS_P]
    __shared__ float ws[CIN][9][16];              // weights, 16 couts, no dup

    const int tid = threadIdx.x;
    const int cg  = tid >> 7;            // 0/1 : cout half
    const int rt  = tid & 127;
    const int ty  = rt >> 4;             // 0..7  : row within band
    const int tx  = rt & 15;             // 0..15 : w-quad
    const int ht  = blockIdx.x * BAND;   // band start row
    const int c0  = (blockIdx.y << 4) + (cg << 3);   // this half's cout base
    const int t   = t0 + blockIdx.z;     // timestep

    const int h0 = ht + ty;
    const int w0 = tx * 4;

    const float* xsrc = x + (size_t)t * (CIN * HH * WWID);

    unsigned xs_u32;
    {
        unsigned long long tmp = __cvta_generic_to_shared(xs);
        xs_u32 = (unsigned)tmp;
    }

    // ---- stage xs rows: column halos zeroed, valid rows via cp.async ----
    for (int rowid = tid; rowid < NROWS; rowid += 256) {
        int cin = rowid / ROWS_S;
        int rr  = rowid - cin * ROWS_S;
        int gh  = ht - 1 + rr;
        float* s = xs + rowid * COLS_P;
        *reinterpret_cast<float4*>(s + 0)  = make_float4(0.f, 0.f, 0.f, 0.f);
        *reinterpret_cast<float4*>(s + 68) = make_float4(0.f, 0.f, 0.f, 0.f);
        if (gh >= 0 && gh < HH) {
            unsigned sdst = xs_u32 + (unsigned)((rowid * COLS_P + XOFF) * 4);
            const char* g = (const char*)(xsrc + cin * (HH * WWID) + gh * WWID);
            #pragma unroll
            for (int k = 0; k < 16; ++k)
                cp16(sdst + k * 16, g + k * 16);
        } else {
            float4* z = reinterpret_cast<float4*>(s + XOFF);
            #pragma unroll
            for (int k = 0; k < 16; ++k)
                z[k] = make_float4(0.f, 0.f, 0.f, 0.f);
        }
    }
    cp_commit();

    // ---- stage weights (non-duplicated): 16*9*16 = 2304 floats ----
    {
        const int cbase = blockIdx.y << 4;
        for (int i = tid; i < CIN * 9 * 16; i += 256) {
            int c   = i & 15;
            int rem = i >> 4;
            int tap = rem % 9;
            int cin = rem / 9;
            ws[cin][tap][c] = Wg[((cbase + c) * CIN + cin) * 9 + tap];
        }
    }

    cp_wait0();
    __syncthreads();

    // accumulators: acc[cp][p] = (out[2cp][p], out[2cp+1][p]) for pixel p
    ull acc[4][4];
    #pragma unroll
    for (int cp = 0; cp < 4; ++cp)
        #pragma unroll
        for (int p = 0; p < 4; ++p) acc[cp][p] = 0ull;

    const int cg8 = cg << 3;

    #pragma unroll 4
    for (int cin = 0; cin < CIN; ++cin) {
        #pragma unroll
        for (int r = 0; r < 3; ++r) {
            const float* rowp = xs + (cin * ROWS_S + ty + r) * COLS_P + XOFF + w0;
            float4 xq = *reinterpret_cast<const float4*>(rowp);   // x0..x3
            float  xm = rowp[-1];                                 // x-1
            float  xp = rowp[4];                                  // x4

            ull xd0 = dup2(xm);
            ull xd1 = dup2(xq.x);
            ull xd2 = dup2(xq.y);
            ull xd3 = dup2(xq.z);
            ull xd4 = dup2(xq.w);
            ull xd5 = dup2(xp);

            // weight pairs: taps kw=0..2, couts cg8..cg8+7 (non-duplicated)
            const ulonglong2* w0v =
                reinterpret_cast<const ulonglong2*>(&ws[cin][r * 3 + 0][cg8]);
            const ulonglong2* w1v =
                reinterpret_cast<const ulonglong2*>(&ws[cin][r * 3 + 1][cg8]);
            const ulonglong2* w2v =
                reinterpret_cast<const ulonglong2*>(&ws[cin][r * 3 + 2][cg8]);
            ulonglong2 Wk0a = w0v[0], Wk0b = w0v[1];  // kw0: cp0,cp1 / cp2,cp3
            ulonglong2 Wk1a = w1v[0], Wk1b = w1v[1];  // kw1
            ulonglong2 Wk2a = w2v[0], Wk2b = w2v[1];  // kw2

            // per-accumulator order: kw0, kw1, kw2 (bit-exact chain)
            fma2(acc[0][0], xd0, Wk0a.x); fma2(acc[0][0], xd1, Wk1a.x); fma2(acc[0][0], xd2, Wk2a.x);
            fma2(acc[0][1], xd1, Wk0a.x); fma2(acc[0][1], xd2, Wk1a.x); fma2(acc[0][1], xd3, Wk2a.x);
            fma2(acc[0][2], xd2, Wk0a.x); fma2(acc[0][2], xd3, Wk1a.x); fma2(acc[0][2], xd4, Wk2a.x);
            fma2(acc[0][3], xd3, Wk0a.x); fma2(acc[0][3], xd4, Wk1a.x); fma2(acc[0][3], xd5, Wk2a.x);

            fma2(acc[1][0], xd0, Wk0a.y); fma2(acc[1][0], xd1, Wk1a.y); fma2(acc[1][0], xd2, Wk2a.y);
            fma2(acc[1][1], xd1, Wk0a.y); fma2(acc[1][1], xd2, Wk1a.y); fma2(acc[1][1], xd3, Wk2a.y);
            fma2(acc[1][2], xd2, Wk0a.y); fma2(acc[1][2], xd3, Wk1a.y); fma2(acc[1][2], xd4, Wk2a.y);
            fma2(acc[1][3], xd3, Wk0a.y); fma2(acc[1][3], xd4, Wk1a.y); fma2(acc[1][3], xd5, Wk2a.y);

            fma2(acc[2][0], xd0, Wk0b.x); fma2(acc[2][0], xd1, Wk1b.x); fma2(acc[2][0], xd2, Wk2b.x);
            fma2(acc[2][1], xd1, Wk0b.x); fma2(acc[2][1], xd2, Wk1b.x); fma2(acc[2][1], xd3, Wk2b.x);
            fma2(acc[2][2], xd2, Wk0b.x); fma2(acc[2][2], xd3, Wk1b.x); fma2(acc[2][2], xd4, Wk2b.x);
            fma2(acc[2][3], xd3, Wk0b.x); fma2(acc[2][3], xd4, Wk1b.x); fma2(acc[2][3], xd5, Wk2b.x);

            fma2(acc[3][0], xd0, Wk0b.y); fma2(acc[3][0], xd1, Wk1b.y); fma2(acc[3][0], xd2, Wk2b.y);
            fma2(acc[3][1], xd1, Wk0b.y); fma2(acc[3][1], xd2, Wk1b.y); fma2(acc[3][1], xd3, Wk2b.y);
            fma2(acc[3][2], xd2, Wk0b.y); fma2(acc[3][2], xd3, Wk1b.y); fma2(acc[3][2], xd4, Wk2b.y);
            fma2(acc[3][3], xd3, Wk0b.y); fma2(acc[3][3], xd4, Wk1b.y); fma2(acc[3][3], xd5, Wk2b.y);
        }
    }

    // ---- write rounded conv_t + b as float4 per cout ----
    float* o = out + (size_t)t * (COUT * HH * WWID)
                   + (size_t)c0 * (HH * WWID) + h0 * WWID + w0;
    #pragma unroll
    for (int cp = 0; cp < 4; ++cp) {
        float lo0, hi0, lo1, hi1, lo2, hi2, lo3, hi3;
        unpack2(acc[cp][0], lo0, hi0);
        unpack2(acc[cp][1], lo1, hi1);
        unpack2(acc[cp][2], lo2, hi2);
        unpack2(acc[cp][3], lo3, hi3);
        const float be = bg[c0 + 2 * cp];
        const float bo = bg[c0 + 2 * cp + 1];
        *reinterpret_cast<float4*>(o + (size_t)(2 * cp) * (HH * WWID)) =
            make_float4(fadd(lo0, be), fadd(lo1, be), fadd(lo2, be), fadd(lo3, be));
        *reinterpret_cast<float4*>(o + (size_t)(2 * cp + 1) * (HH * WWID)) =
            make_float4(fadd(hi0, bo), fadd(hi1, bo), fadd(hi2, bo), fadd(hi3, bo));
    }
}

// ---------------- K2: in-place LIF scan over t (float4) ---------------------
__global__ __launch_bounds__(256)
void scan_kernel(float* __restrict__ out)
{
    const int idx = blockIdx.x * 256 + threadIdx.x;   // float4 element index
    float4* p = reinterpret_cast<float4*>(out) + idx;
    const int stride4 = (COUT * HH * WWID) / 4;

    float4 s = make_float4(0.f, 0.f, 0.f, 0.f);
    #pragma unroll 4
    for (int t = 0; t < T_STEPS; ++t) {
        float4 c = p[(size_t)t * stride4];
        float4 v;
        v.x = fadd(s.x, c.x); v.y = fadd(s.y, c.y);
        v.z = fadd(s.z, c.z); v.w = fadd(s.w, c.w);
        float4 k;
        k.x = (v.x >= 8.f) ? 1.f : 0.f;  k.y = (v.y >= 8.f) ? 1.f : 0.f;
        k.z = (v.z >= 8.f) ? 1.f : 0.f;  k.w = (v.w >= 8.f) ? 1.f : 0.f;
        v.x = (v.x >= 8.f) ? 0.f : v.x;  v.y = (v.y >= 8.f) ? 0.f : v.y;
        v.z = (v.z >= 8.f) ? 0.f : v.z;  v.w = (v.w >= 8.f) ? 0.f : v.w;
        s.x = fmaxf(v.x, -1.f);          s.y = fmaxf(v.y, -1.f);
        s.z = fmaxf(v.z, -1.f);          s.w = fmaxf(v.w, -1.f);
        p[(size_t)t * stride4] = k;
    }
}

extern "C" void kernel_launch(void* const* d_in, const int* in_sizes, int n_in,
                              void* d_out, int out_size)
{
    const float* x  = (const float*)d_in[0];   // [128,16,64,64]
    const float* Wg = (const float*)d_in[1];   // [64,16,3,3]
    const float* bg = (const float*)d_in[2];   // [64]
    float* out      = (float*)d_out;           // [128,64,64,64]

    static int attr_set = 0;
    size_t xs_bytes = (size_t)XS_FLOATS * sizeof(float);   // 46080 B
    if (!attr_set) {
        cudaFuncSetAttribute(conv_kernel,
                             cudaFuncAttributeMaxDynamicSharedMemorySize,
                             (int)xs_bytes);
        attr_set = 1;
    }

    // 4 t-chunk launches: keeps ncu's sampled launch on conv (4/5 odds).
    dim3 grid1(8, 4, 32);   // 8 row bands x 4 cout-pairs x 32 timesteps
    conv_kernel<<<grid1, 256, xs_bytes>>>(x, Wg, bg, out, 0);
    conv_kernel<<<grid1, 256, xs_bytes>>>(x, Wg, bg, out, 32);
    conv_kernel<<<grid1, 256, xs_bytes>>>(x, Wg, bg, out, 64);
    conv_kernel<<<grid1, 256, xs_bytes>>>(x, Wg, bg, out, 96);

    scan_kernel<<<(COUT * HH * WWID) / 4 / 256, 256>>>(out);
}

// round 13
// speedup vs baseline: 2.2399x; 1.1631x over previous
#include <cuda_runtime.h>

// Two-kernel fused spiking conv2d (T=128, Cin=16, Cout=64, 64x64, pad=1) + LIF.
// K1: conv+bias, single launch (4096 blocks -> 9.2 waves at 3 blocks/SM,
//     killing the 4x ~2.3-wave tail quantization of the chunked version).
//     f32x2 lanes = cout-pairs; weights non-duplicated (6 LDS.128/iter);
//     x duplicated via ALU MOVs; single padded x buffer.
// K2: in-place float4 LIF scan with streaming (.cs) hints.
// Bit-exact: per-output (cin,kh,kw) fma2 chain + (conv+b) then (state+conv).

#define T_STEPS 128
#define CIN     16
#define HH      64
#define WWID    64
#define COUT    64

#define BAND    8               // output rows per block
#define ROWS_S  10              // band + top/bottom halo rows
#define COLS_P  72              // 4 left-pad + 64 + 4 right-pad
#define XOFF    4               // column c stored at [XOFF + c]
#define NROWS   (CIN * ROWS_S)  // 160 staged rows
#define XS_FLOATS (NROWS * COLS_P)   // 11520 floats = 46080 B

typedef unsigned long long ull;

__device__ __forceinline__ void fma2(ull& d, ull a, ull b) {
    asm("fma.rn.f32x2 %0, %1, %2, %0;" : "+l"(d) : "l"(a), "l"(b));
}
__device__ __forceinline__ ull dup2(float v) {
    ull r;
    asm("mov.b64 %0, {%1, %1};" : "=l"(r) : "f"(v));
    return r;
}
__device__ __forceinline__ void unpack2(ull v, float& lo, float& hi) {
    asm("mov.b64 {%0, %1}, %2;" : "=f"(lo), "=f"(hi) : "l"(v));
}
__device__ __forceinline__ float fadd(float a, float b) {
    float r;
    asm("add.rn.f32 %0, %1, %2;" : "=f"(r) : "f"(a), "f"(b));
    return r;
}
__device__ __forceinline__ void cp16(unsigned saddr, const void* g) {
    asm volatile("cp.async.cg.shared.global [%0], [%1], 16;"
                 :: "r"(saddr), "l"(g));
}
__device__ __forceinline__ void cp_commit() {
    asm volatile("cp.async.commit_group;");
}
__device__ __forceinline__ void cp_wait0() {
    asm volatile("cp.async.wait_group 0;");
}

// ---------------- K1: conv + bias ------------------------------------------
// Block: 256 threads = 2 cout-halves x (8 ty rows x 16 tx quads).
// Grid: (8 row-bands, 4 cout-pairs, 128 timesteps) -- single launch.
__global__ __launch_bounds__(256, 3)
void conv_kernel(const float* __restrict__ x,
                 const float* __restrict__ Wg,
                 const float* __restrict__ bg,
                 float* __restrict__ out)
{
    extern __shared__ float xs[];                 // [NROWS][COLS_P]
    __shared__ float ws[CIN][9][16];              // weights, 16 couts, no dup

    const int tid = threadIdx.x;
    const int cg  = tid >> 7;            // 0/1 : cout half
    const int rt  = tid & 127;
    const int ty  = rt >> 4;             // 0..7  : row within band
    const int tx  = rt & 15;             // 0..15 : w-quad
    const int ht  = blockIdx.x * BAND;   // band start row
    const int c0  = (blockIdx.y << 4) + (cg << 3);   // this half's cout base
    const int t   = blockIdx.z;          // timestep

    const int h0 = ht + ty;
    const int w0 = tx * 4;

    const float* xsrc = x + (size_t)t * (CIN * HH * WWID);

    unsigned xs_u32;
    {
        unsigned long long tmp = __cvta_generic_to_shared(xs);
        xs_u32 = (unsigned)tmp;
    }

    // ---- stage xs rows: column halos zeroed, valid rows via cp.async ----
    for (int rowid = tid; rowid < NROWS; rowid += 256) {
        int cin = rowid / ROWS_S;
        int rr  = rowid - cin * ROWS_S;
        int gh  = ht - 1 + rr;
        float* s = xs + rowid * COLS_P;
        *reinterpret_cast<float4*>(s + 0)  = make_float4(0.f, 0.f, 0.f, 0.f);
        *reinterpret_cast<float4*>(s + 68) = make_float4(0.f, 0.f, 0.f, 0.f);
        if (gh >= 0 && gh < HH) {
            unsigned sdst = xs_u32 + (unsigned)((rowid * COLS_P + XOFF) * 4);
            const char* g = (const char*)(xsrc + cin * (HH * WWID) + gh * WWID);
            #pragma unroll
            for (int k = 0; k < 16; ++k)
                cp16(sdst + k * 16, g + k * 16);
        } else {
            float4* z = reinterpret_cast<float4*>(s + XOFF);
            #pragma unroll
            for (int k = 0; k < 16; ++k)
                z[k] = make_float4(0.f, 0.f, 0.f, 0.f);
        }
    }
    cp_commit();

    // ---- stage weights (non-duplicated): 16*9*16 = 2304 floats ----
    {
        const int cbase = blockIdx.y << 4;
        for (int i = tid; i < CIN * 9 * 16; i += 256) {
            int c   = i & 15;
            int rem = i >> 4;
            int tap = rem % 9;
            int cin = rem / 9;
            ws[cin][tap][c] = Wg[((cbase + c) * CIN + cin) * 9 + tap];
        }
    }

    cp_wait0();
    __syncthreads();

    // accumulators: acc[cp][p] = (out[2cp][p], out[2cp+1][p]) for pixel p
    ull acc[4][4];
    #pragma unroll
    for (int cp = 0; cp < 4; ++cp)
        #pragma unroll
        for (int p = 0; p < 4; ++p) acc[cp][p] = 0ull;

    const int cg8 = cg << 3;

    #pragma unroll 4
    for (int cin = 0; cin < CIN; ++cin) {
        #pragma unroll
        for (int r = 0; r < 3; ++r) {
            const float* rowp = xs + (cin * ROWS_S + ty + r) * COLS_P + XOFF + w0;
            float4 xq = *reinterpret_cast<const float4*>(rowp);   // x0..x3
            float  xm = rowp[-1];                                 // x-1
            float  xp = rowp[4];                                  // x4

            ull xd0 = dup2(xm);
            ull xd1 = dup2(xq.x);
            ull xd2 = dup2(xq.y);
            ull xd3 = dup2(xq.z);
            ull xd4 = dup2(xq.w);
            ull xd5 = dup2(xp);

            const ulonglong2* w0v =
                reinterpret_cast<const ulonglong2*>(&ws[cin][r * 3 + 0][cg8]);
            const ulonglong2* w1v =
                reinterpret_cast<const ulonglong2*>(&ws[cin][r * 3 + 1][cg8]);
            const ulonglong2* w2v =
                reinterpret_cast<const ulonglong2*>(&ws[cin][r * 3 + 2][cg8]);
            ulonglong2 Wk0a = w0v[0], Wk0b = w0v[1];
            ulonglong2 Wk1a = w1v[0], Wk1b = w1v[1];
            ulonglong2 Wk2a = w2v[0], Wk2b = w2v[1];

            // per-accumulator order: kw0, kw1, kw2 (bit-exact chain)
            fma2(acc[0][0], xd0, Wk0a.x); fma2(acc[0][0], xd1, Wk1a.x); fma2(acc[0][0], xd2, Wk2a.x);
            fma2(acc[0][1], xd1, Wk0a.x); fma2(acc[0][1], xd2, Wk1a.x); fma2(acc[0][1], xd3, Wk2a.x);
            fma2(acc[0][2], xd2, Wk0a.x); fma2(acc[0][2], xd3, Wk1a.x); fma2(acc[0][2], xd4, Wk2a.x);
            fma2(acc[0][3], xd3, Wk0a.x); fma2(acc[0][3], xd4, Wk1a.x); fma2(acc[0][3], xd5, Wk2a.x);

            fma2(acc[1][0], xd0, Wk0a.y); fma2(acc[1][0], xd1, Wk1a.y); fma2(acc[1][0], xd2, Wk2a.y);
            fma2(acc[1][1], xd1, Wk0a.y); fma2(acc[1][1], xd2, Wk1a.y); fma2(acc[1][1], xd3, Wk2a.y);
            fma2(acc[1][2], xd2, Wk0a.y); fma2(acc[1][2], xd3, Wk1a.y); fma2(acc[1][2], xd4, Wk2a.y);
            fma2(acc[1][3], xd3, Wk0a.y); fma2(acc[1][3], xd4, Wk1a.y); fma2(acc[1][3], xd5, Wk2a.y);

            fma2(acc[2][0], xd0, Wk0b.x); fma2(acc[2][0], xd1, Wk1b.x); fma2(acc[2][0], xd2, Wk2b.x);
            fma2(acc[2][1], xd1, Wk0b.x); fma2(acc[2][1], xd2, Wk1b.x); fma2(acc[2][1], xd3, Wk2b.x);
            fma2(acc[2][2], xd2, Wk0b.x); fma2(acc[2][2], xd3, Wk1b.x); fma2(acc[2][2], xd4, Wk2b.x);
            fma2(acc[2][3], xd3, Wk0b.x); fma2(acc[2][3], xd4, Wk1b.x); fma2(acc[2][3], xd5, Wk2b.x);

            fma2(acc[3][0], xd0, Wk0b.y); fma2(acc[3][0], xd1, Wk1b.y); fma2(acc[3][0], xd2, Wk2b.y);
            fma2(acc[3][1], xd1, Wk0b.y); fma2(acc[3][1], xd2, Wk1b.y); fma2(acc[3][1], xd3, Wk2b.y);
            fma2(acc[3][2], xd2, Wk0b.y); fma2(acc[3][2], xd3, Wk1b.y); fma2(acc[3][2], xd4, Wk2b.y);
            fma2(acc[3][3], xd3, Wk0b.y); fma2(acc[3][3], xd4, Wk1b.y); fma2(acc[3][3], xd5, Wk2b.y);
        }
    }

    // ---- write rounded conv_t + b as float4 per cout ----
    float* o = out + (size_t)t * (COUT * HH * WWID)
                   + (size_t)c0 * (HH * WWID) + h0 * WWID + w0;
    #pragma unroll
    for (int cp = 0; cp < 4; ++cp) {
        float lo0, hi0, lo1, hi1, lo2, hi2, lo3, hi3;
        unpack2(acc[cp][0], lo0, hi0);
        unpack2(acc[cp][1], lo1, hi1);
        unpack2(acc[cp][2], lo2, hi2);
        unpack2(acc[cp][3], lo3, hi3);
        const float be = bg[c0 + 2 * cp];
        const float bo = bg[c0 + 2 * cp + 1];
        *reinterpret_cast<float4*>(o + (size_t)(2 * cp) * (HH * WWID)) =
            make_float4(fadd(lo0, be), fadd(lo1, be), fadd(lo2, be), fadd(lo3, be));
        *reinterpret_cast<float4*>(o + (size_t)(2 * cp + 1) * (HH * WWID)) =
            make_float4(fadd(hi0, bo), fadd(hi1, bo), fadd(hi2, bo), fadd(hi3, bo));
    }
}

// ---------------- K2: in-place LIF scan over t (float4, streaming) ----------
__global__ __launch_bounds__(256)
void scan_kernel(float* __restrict__ out)
{
    const int idx = blockIdx.x * 256 + threadIdx.x;   // float4 element index
    float4* p = reinterpret_cast<float4*>(out) + idx;
    const int stride4 = (COUT * HH * WWID) / 4;

    float4 s = make_float4(0.f, 0.f, 0.f, 0.f);
    #pragma unroll 4
    for (int t = 0; t < T_STEPS; ++t) {
        float4 c = __ldcs(p + (size_t)t * stride4);
        float4 v;
        v.x = fadd(s.x, c.x); v.y = fadd(s.y, c.y);
        v.z = fadd(s.z, c.z); v.w = fadd(s.w, c.w);
        float4 k;
        k.x = (v.x >= 8.f) ? 1.f : 0.f;  k.y = (v.y >= 8.f) ? 1.f : 0.f;
        k.z = (v.z >= 8.f) ? 1.f : 0.f;  k.w = (v.w >= 8.f) ? 1.f : 0.f;
        v.x = (v.x >= 8.f) ? 0.f : v.x;  v.y = (v.y >= 8.f) ? 0.f : v.y;
        v.z = (v.z >= 8.f) ? 0.f : v.z;  v.w = (v.w >= 8.f) ? 0.f : v.w;
        s.x = fmaxf(v.x, -1.f);          s.y = fmaxf(v.y, -1.f);
        s.z = fmaxf(v.z, -1.f);          s.w = fmaxf(v.w, -1.f);
        __stcs(p + (size_t)t * stride4, k);
    }
}

extern "C" void kernel_launch(void* const* d_in, const int* in_sizes, int n_in,
                              void* d_out, int out_size)
{
    const float* x  = (const float*)d_in[0];   // [128,16,64,64]
    const float* Wg = (const float*)d_in[1];   // [64,16,3,3]
    const float* bg = (const float*)d_in[2];   // [64]
    float* out      = (float*)d_out;           // [128,64,64,64]

    static int attr_set = 0;
    size_t xs_bytes = (size_t)XS_FLOATS * sizeof(float);   // 46080 B
    if (!attr_set) {
        cudaFuncSetAttribute(conv_kernel,
                             cudaFuncAttributeMaxDynamicSharedMemorySize,
                             (int)xs_bytes);
        attr_set = 1;
    }

    // single conv launch: 4096 blocks -> 9.2 waves at 3 blocks/SM (tiny tail)
    dim3 grid1(8, 4, T_STEPS);
    conv_kernel<<<grid1, 256, xs_bytes>>>(x, Wg, bg, out);

    scan_kernel<<<(COUT * HH * WWID) / 4 / 256, 256>>>(out);
}

// round 14
// speedup vs baseline: 2.2538x; 1.0062x over previous
#include <cuda_runtime.h>

// Two-kernel fused spiking conv2d (T=128, Cin=16, Cout=64, 64x64, pad=1) + LIF.
// K1: conv+bias, single launch. f32x2 lanes = cout-pairs; weights
//     non-duplicated (6 LDS.128/iter); x dup via ALU MOVs.
//     Staging split into two cp.async commit groups (cin 0-7 / 8-15):
//     compute on the first half starts while the second half is in flight.
// K2: in-place LIF scan, 8-deep load batching (MLP=8) + 64-thread blocks
//     (1024 blocks -> 14% imbalance instead of 2:1 at 256 blocks).
// Bit-exact: per-output (cin,kh,kw) fma2 chain + (conv+b) then (state+conv).

#define T_STEPS 128
#define CIN     16
#define HH      64
#define WWID    64
#define COUT    64

#define BAND    8               // output rows per block
#define ROWS_S  10              // band + top/bottom halo rows
#define COLS_P  72              // 4 left-pad + 64 + 4 right-pad
#define XOFF    4               // column c stored at [XOFF + c]
#define NROWS   (CIN * ROWS_S)  // 160 staged rows
#define HROWS   (NROWS / 2)     // 80 rows per cin-half
#define XS_FLOATS (NROWS * COLS_P)   // 11520 floats = 46080 B

typedef unsigned long long ull;

__device__ __forceinline__ void fma2(ull& d, ull a, ull b) {
    asm("fma.rn.f32x2 %0, %1, %2, %0;" : "+l"(d) : "l"(a), "l"(b));
}
__device__ __forceinline__ ull dup2(float v) {
    ull r;
    asm("mov.b64 %0, {%1, %1};" : "=l"(r) : "f"(v));
    return r;
}
__device__ __forceinline__ void unpack2(ull v, float& lo, float& hi) {
    asm("mov.b64 {%0, %1}, %2;" : "=f"(lo), "=f"(hi) : "l"(v));
}
__device__ __forceinline__ float fadd(float a, float b) {
    float r;
    asm("add.rn.f32 %0, %1, %2;" : "=f"(r) : "f"(a), "f"(b));
    return r;
}
__device__ __forceinline__ void cp16(unsigned saddr, const void* g) {
    asm volatile("cp.async.cg.shared.global [%0], [%1], 16;"
                 :: "r"(saddr), "l"(g));
}
__device__ __forceinline__ void cp_commit() {
    asm volatile("cp.async.commit_group;");
}
__device__ __forceinline__ void cp_wait_all() {
    asm volatile("cp.async.wait_group 0;");
}
__device__ __forceinline__ void cp_wait_1() {
    asm volatile("cp.async.wait_group 1;");
}

// Stage one smem row (halo-zeroed, cp.async for valid image rows).
__device__ __forceinline__ void stage_row(float* xs, unsigned xs_u32,
                                          const float* xsrc, int rowid, int ht)
{
    int cin = rowid / ROWS_S;
    int rr  = rowid - cin * ROWS_S;
    int gh  = ht - 1 + rr;
    float* s = xs + rowid * COLS_P;
    *reinterpret_cast<float4*>(s + 0)  = make_float4(0.f, 0.f, 0.f, 0.f);
    *reinterpret_cast<float4*>(s + 68) = make_float4(0.f, 0.f, 0.f, 0.f);
    if (gh >= 0 && gh < HH) {
        unsigned sdst = xs_u32 + (unsigned)((rowid * COLS_P + XOFF) * 4);
        const char* g = (const char*)(xsrc + cin * (HH * WWID) + gh * WWID);
        #pragma unroll
        for (int k = 0; k < 16; ++k)
            cp16(sdst + k * 16, g + k * 16);
    } else {
        float4* z = reinterpret_cast<float4*>(s + XOFF);
        #pragma unroll
        for (int k = 0; k < 16; ++k)
            z[k] = make_float4(0.f, 0.f, 0.f, 0.f);
    }
}

// ---------------- K1: conv + bias ------------------------------------------
// Block: 256 threads = 2 cout-halves x (8 ty rows x 16 tx quads).
// Grid: (8 row-bands, 4 cout-pairs, 128 timesteps) -- single launch.
__global__ __launch_bounds__(256, 3)
void conv_kernel(const float* __restrict__ x,
                 const float* __restrict__ Wg,
                 const float* __restrict__ bg,
                 float* __restrict__ out)
{
    extern __shared__ float xs[];                 // [NROWS][COLS_P]
    __shared__ float ws[CIN][9][16];              // weights, 16 couts, no dup

    const int tid = threadIdx.x;
    const int cg  = tid >> 7;            // 0/1 : cout half
    const int rt  = tid & 127;
    const int ty  = rt >> 4;             // 0..7  : row within band
    const int tx  = rt & 15;             // 0..15 : w-quad
    const int ht  = blockIdx.x * BAND;   // band start row
    const int c0  = (blockIdx.y << 4) + (cg << 3);   // this half's cout base
    const int t   = blockIdx.z;          // timestep

    const int h0 = ht + ty;
    const int w0 = tx * 4;

    const float* xsrc = x + (size_t)t * (CIN * HH * WWID);

    unsigned xs_u32;
    {
        unsigned long long tmp = __cvta_generic_to_shared(xs);
        xs_u32 = (unsigned)tmp;
    }

    // ---- stage chunk A (cin 0..7) -> commit group A ----
    if (tid < HROWS) stage_row(xs, xs_u32, xsrc, tid, ht);
    cp_commit();
    // ---- stage chunk B (cin 8..15) -> commit group B ----
    if (tid < HROWS) stage_row(xs, xs_u32, xsrc, HROWS + tid, ht);
    cp_commit();

    // ---- stage weights (non-duplicated): 16*9*16 = 2304 floats ----
    {
        const int cbase = blockIdx.y << 4;
        for (int i = tid; i < CIN * 9 * 16; i += 256) {
            int c   = i & 15;
            int rem = i >> 4;
            int tap = rem % 9;
            int cin = rem / 9;
            ws[cin][tap][c] = Wg[((cbase + c) * CIN + cin) * 9 + tap];
        }
    }

    // accumulators: acc[cp][p] = (out[2cp][p], out[2cp+1][p]) for pixel p
    ull acc[4][4];
    #pragma unroll
    for (int cp = 0; cp < 4; ++cp)
        #pragma unroll
        for (int p = 0; p < 4; ++p) acc[cp][p] = 0ull;

    const int cg8 = cg << 3;

    // chunk A ready (group B may still be in flight)
    cp_wait_1();
    __syncthreads();

    #pragma unroll 1
    for (int half = 0; half < 2; ++half) {
        const int cbeg = half * (CIN / 2);
        #pragma unroll 4
        for (int ci = 0; ci < CIN / 2; ++ci) {
            const int cin = cbeg + ci;
            #pragma unroll
            for (int r = 0; r < 3; ++r) {
                const float* rowp = xs + (cin * ROWS_S + ty + r) * COLS_P + XOFF + w0;
                float4 xq = *reinterpret_cast<const float4*>(rowp);   // x0..x3
                float  xm = rowp[-1];                                 // x-1
                float  xp = rowp[4];                                  // x4

                ull xd0 = dup2(xm);
                ull xd1 = dup2(xq.x);
                ull xd2 = dup2(xq.y);
                ull xd3 = dup2(xq.z);
                ull xd4 = dup2(xq.w);
                ull xd5 = dup2(xp);

                const ulonglong2* w0v =
                    reinterpret_cast<const ulonglong2*>(&ws[cin][r * 3 + 0][cg8]);
                const ulonglong2* w1v =
                    reinterpret_cast<const ulonglong2*>(&ws[cin][r * 3 + 1][cg8]);
                const ulonglong2* w2v =
                    reinterpret_cast<const ulonglong2*>(&ws[cin][r * 3 + 2][cg8]);
                ulonglong2 Wk0a = w0v[0], Wk0b = w0v[1];
                ulonglong2 Wk1a = w1v[0], Wk1b = w1v[1];
                ulonglong2 Wk2a = w2v[0], Wk2b = w2v[1];

                // per-accumulator order: kw0, kw1, kw2 (bit-exact chain)
                fma2(acc[0][0], xd0, Wk0a.x); fma2(acc[0][0], xd1, Wk1a.x); fma2(acc[0][0], xd2, Wk2a.x);
                fma2(acc[0][1], xd1, Wk0a.x); fma2(acc[0][1], xd2, Wk1a.x); fma2(acc[0][1], xd3, Wk2a.x);
                fma2(acc[0][2], xd2, Wk0a.x); fma2(acc[0][2], xd3, Wk1a.x); fma2(acc[0][2], xd4, Wk2a.x);
                fma2(acc[0][3], xd3, Wk0a.x); fma2(acc[0][3], xd4, Wk1a.x); fma2(acc[0][3], xd5, Wk2a.x);

                fma2(acc[1][0], xd0, Wk0a.y); fma2(acc[1][0], xd1, Wk1a.y); fma2(acc[1][0], xd2, Wk2a.y);
                fma2(acc[1][1], xd1, Wk0a.y); fma2(acc[1][1], xd2, Wk1a.y); fma2(acc[1][1], xd3, Wk2a.y);
                fma2(acc[1][2], xd2, Wk0a.y); fma2(acc[1][2], xd3, Wk1a.y); fma2(acc[1][2], xd4, Wk2a.y);
                fma2(acc[1][3], xd3, Wk0a.y); fma2(acc[1][3], xd4, Wk1a.y); fma2(acc[1][3], xd5, Wk2a.y);

                fma2(acc[2][0], xd0, Wk0b.x); fma2(acc[2][0], xd1, Wk1b.x); fma2(acc[2][0], xd2, Wk2b.x);
                fma2(acc[2][1], xd1, Wk0b.x); fma2(acc[2][1], xd2, Wk1b.x); fma2(acc[2][1], xd3, Wk2b.x);
                fma2(acc[2][2], xd2, Wk0b.x); fma2(acc[2][2], xd3, Wk1b.x); fma2(acc[2][2], xd4, Wk2b.x);
                fma2(acc[2][3], xd3, Wk0b.x); fma2(acc[2][3], xd4, Wk1b.x); fma2(acc[2][3], xd5, Wk2b.x);

                fma2(acc[3][0], xd0, Wk0b.y); fma2(acc[3][0], xd1, Wk1b.y); fma2(acc[3][0], xd2, Wk2b.y);
                fma2(acc[3][1], xd1, Wk0b.y); fma2(acc[3][1], xd2, Wk1b.y); fma2(acc[3][1], xd3, Wk2b.y);
                fma2(acc[3][2], xd2, Wk0b.y); fma2(acc[3][2], xd3, Wk1b.y); fma2(acc[3][2], xd4, Wk2b.y);
                fma2(acc[3][3], xd3, Wk0b.y); fma2(acc[3][3], xd4, Wk1b.y); fma2(acc[3][3], xd5, Wk2b.y);
            }
        }
        if (half == 0) {
            // chunk B ready before its first read
            cp_wait_all();
            __syncthreads();
        }
    }

    // ---- write rounded conv_t + b as float4 per cout ----
    float* o = out + (size_t)t * (COUT * HH * WWID)
                   + (size_t)c0 * (HH * WWID) + h0 * WWID + w0;
    #pragma unroll
    for (int cp = 0; cp < 4; ++cp) {
        float lo0, hi0, lo1, hi1, lo2, hi2, lo3, hi3;
        unpack2(acc[cp][0], lo0, hi0);
        unpack2(acc[cp][1], lo1, hi1);
        unpack2(acc[cp][2], lo2, hi2);
        unpack2(acc[cp][3], lo3, hi3);
        const float be = bg[c0 + 2 * cp];
        const float bo = bg[c0 + 2 * cp + 1];
        *reinterpret_cast<float4*>(o + (size_t)(2 * cp) * (HH * WWID)) =
            make_float4(fadd(lo0, be), fadd(lo1, be), fadd(lo2, be), fadd(lo3, be));
        *reinterpret_cast<float4*>(o + (size_t)(2 * cp + 1) * (HH * WWID)) =
            make_float4(fadd(hi0, bo), fadd(hi1, bo), fadd(hi2, bo), fadd(hi3, bo));
    }
}

// ---------------- K2: in-place LIF scan over t (float4, MLP=8) --------------
__global__ __launch_bounds__(64)
void scan_kernel(float* __restrict__ out)
{
    const int idx = blockIdx.x * 64 + threadIdx.x;   // float4 element index
    float4* p = reinterpret_cast<float4*>(out) + idx;
    const int stride4 = (COUT * HH * WWID) / 4;

    float4 s = make_float4(0.f, 0.f, 0.f, 0.f);
    #pragma unroll 1
    for (int tb = 0; tb < T_STEPS; tb += 8) {
        float4 c[8];
        #pragma unroll
        for (int u = 0; u < 8; ++u)
            c[u] = __ldcs(p + (size_t)(tb + u) * stride4);
        #pragma unroll
        for (int u = 0; u < 8; ++u) {
            float4 v;
            v.x = fadd(s.x, c[u].x); v.y = fadd(s.y, c[u].y);
            v.z = fadd(s.z, c[u].z); v.w = fadd(s.w, c[u].w);
            float4 k;
            k.x = (v.x >= 8.f) ? 1.f : 0.f;  k.y = (v.y >= 8.f) ? 1.f : 0.f;
            k.z = (v.z >= 8.f) ? 1.f : 0.f;  k.w = (v.w >= 8.f) ? 1.f : 0.f;
            v.x = (v.x >= 8.f) ? 0.f : v.x;  v.y = (v.y >= 8.f) ? 0.f : v.y;
            v.z = (v.z >= 8.f) ? 0.f : v.z;  v.w = (v.w >= 8.f) ? 0.f : v.w;
            s.x = fmaxf(v.x, -1.f);          s.y = fmaxf(v.y, -1.f);
            s.z = fmaxf(v.z, -1.f);          s.w = fmaxf(v.w, -1.f);
            __stcs(p + (size_t)(tb + u) * stride4, k);
        }
    }
}

extern "C" void kernel_launch(void* const* d_in, const int* in_sizes, int n_in,
                              void* d_out, int out_size)
{
    const float* x  = (const float*)d_in[0];   // [128,16,64,64]
    const float* Wg = (const float*)d_in[1];   // [64,16,3,3]
    const float* bg = (const float*)d_in[2];   // [64]
    float* out      = (float*)d_out;           // [128,64,64,64]

    static int attr_set = 0;
    size_t xs_bytes = (size_t)XS_FLOATS * sizeof(float);   // 46080 B
    if (!attr_set) {
        cudaFuncSetAttribute(conv_kernel,
                             cudaFuncAttributeMaxDynamicSharedMemorySize,
                             (int)xs_bytes);
        attr_set = 1;
    }

    dim3 grid1(8, 4, T_STEPS);
    conv_kernel<<<grid1, 256, xs_bytes>>>(x, Wg, bg, out);

    scan_kernel<<<(COUT * HH * WWID) / 4 / 64, 64>>>(out);
}

// round 15
// speedup vs baseline: 2.3250x; 1.0316x over previous
#include <cuda_runtime.h>

// Two-kernel fused spiking conv2d (T=128, Cin=16, Cout=64, 64x64, pad=1) + LIF.
// K1: conv+bias, single launch. f32x2 lanes = cout-pairs; weights
//     non-duplicated; x dup via ALU MOVs. Staging rebalanced (R14 finding):
//     - x tile staged as 16B chunks by ALL 256 threads (was 80), A/B split;
//     - weights loaded as coalesced float4 from the contiguous 16-cout span,
//       scattered to smem (was a 32-line-per-warp uncoalesced gather).
// K2: in-place LIF scan (MLP=8, 64-thr blocks) -- at its RMW floor.
// Bit-exact: per-output (cin,kh,kw) fma2 chain + (conv+b) then (state+conv).

#define T_STEPS 128
#define CIN     16
#define HH      64
#define WWID    64
#define COUT    64

#define BAND    8               // output rows per block
#define ROWS_S  10              // band + top/bottom halo rows
#define COLS_P  72              // 4 left-pad + 64 + 4 right-pad
#define XOFF    4               // column c stored at [XOFF + c]
#define NROWS   (CIN * ROWS_S)  // 160 staged rows
#define XS_FLOATS (NROWS * COLS_P)   // 11520 floats = 46080 B
#define DCHUNKS (NROWS * 16)    // 2560 16B data chunks
#define HCHUNKS (DCHUNKS / 2)   // 1280 per A/B half

typedef unsigned long long ull;

__device__ __forceinline__ void fma2(ull& d, ull a, ull b) {
    asm("fma.rn.f32x2 %0, %1, %2, %0;" : "+l"(d) : "l"(a), "l"(b));
}
__device__ __forceinline__ ull dup2(float v) {
    ull r;
    asm("mov.b64 %0, {%1, %1};" : "=l"(r) : "f"(v));
    return r;
}
__device__ __forceinline__ void unpack2(ull v, float& lo, float& hi) {
    asm("mov.b64 {%0, %1}, %2;" : "=f"(lo), "=f"(hi) : "l"(v));
}
__device__ __forceinline__ float fadd(float a, float b) {
    float r;
    asm("add.rn.f32 %0, %1, %2;" : "=f"(r) : "f"(a), "f"(b));
    return r;
}
__device__ __forceinline__ void cp16(unsigned saddr, const void* g) {
    asm volatile("cp.async.cg.shared.global [%0], [%1], 16;"
                 :: "r"(saddr), "l"(g));
}
__device__ __forceinline__ void cp_commit() {
    asm volatile("cp.async.commit_group;");
}
__device__ __forceinline__ void cp_wait_all() {
    asm volatile("cp.async.wait_group 0;");
}
__device__ __forceinline__ void cp_wait_1() {
    asm volatile("cp.async.wait_group 1;");
}

// Stage one 16B data chunk (chunk kk of row rowid).
__device__ __forceinline__ void stage_chunk(float* xs, unsigned xs_u32,
                                            const float* xsrc, int k, int ht)
{
    int rowid = k >> 4;
    int kk    = k & 15;
    int cin   = rowid / ROWS_S;
    int rr    = rowid - cin * ROWS_S;
    int gh    = ht - 1 + rr;
    int soff  = rowid * COLS_P + XOFF + kk * 4;
    if (gh >= 0 && gh < HH) {
        cp16(xs_u32 + (unsigned)(soff * 4),
             xsrc + cin * (HH * WWID) + gh * WWID + kk * 4);
    } else {
        *reinterpret_cast<float4*>(xs + soff) = make_float4(0.f, 0.f, 0.f, 0.f);
    }
}

// ---------------- K1: conv + bias ------------------------------------------
// Block: 256 threads = 2 cout-halves x (8 ty rows x 16 tx quads).
// Grid: (8 row-bands, 4 cout-pairs, 128 timesteps) -- single launch.
__global__ __launch_bounds__(256, 3)
void conv_kernel(const float* __restrict__ x,
                 const float* __restrict__ Wg,
                 const float* __restrict__ bg,
                 float* __restrict__ out)
{
    extern __shared__ float xs[];                 // [NROWS][COLS_P]
    __shared__ float ws[CIN][9][16];              // weights, 16 couts, no dup

    const int tid = threadIdx.x;
    const int cg  = tid >> 7;            // 0/1 : cout half
    const int rt  = tid & 127;
    const int ty  = rt >> 4;             // 0..7  : row within band
    const int tx  = rt & 15;             // 0..15 : w-quad
    const int ht  = blockIdx.x * BAND;   // band start row
    const int c0  = (blockIdx.y << 4) + (cg << 3);   // this half's cout base
    const int t   = blockIdx.z;          // timestep

    const int h0 = ht + ty;
    const int w0 = tx * 4;

    const float* xsrc = x + (size_t)t * (CIN * HH * WWID);

    unsigned xs_u32;
    {
        unsigned long long tmp = __cvta_generic_to_shared(xs);
        xs_u32 = (unsigned)tmp;
    }

    // ---- x data chunks: all 256 threads, A half then B half ----
    #pragma unroll
    for (int j = 0; j < 5; ++j)
        stage_chunk(xs, xs_u32, xsrc, tid + 256 * j, ht);
    cp_commit();
    #pragma unroll
    for (int j = 0; j < 5; ++j)
        stage_chunk(xs, xs_u32, xsrc, HCHUNKS + tid + 256 * j, ht);
    cp_commit();

    // ---- zero the 320 pad chunks (left/right halo columns) ----
    for (int i = tid; i < NROWS * 2; i += 256) {
        int row  = i >> 1;
        int side = i & 1;
        *reinterpret_cast<float4*>(xs + row * COLS_P + side * 68) =
            make_float4(0.f, 0.f, 0.f, 0.f);
    }

    // ---- weights: coalesced float4 load of the contiguous 16-cout span ----
    {
        const float4* wsrc = reinterpret_cast<const float4*>(
            Wg + (size_t)(blockIdx.y << 4) * (CIN * 9));   // 2304 floats
        for (int i4 = tid; i4 < 576; i4 += 256) {
            float4 wv = __ldg(wsrc + i4);
            int flat = i4 * 4;
            #pragma unroll
            for (int u = 0; u < 4; ++u) {
                int idx = flat + u;
                int c   = idx / 144;            // cout local
                int rem = idx - c * 144;
                int cin = rem / 9;
                int tap = rem - cin * 9;
                ws[cin][tap][c] = (&wv.x)[u];
            }
        }
    }

    // accumulators: acc[cp][p] = (out[2cp][p], out[2cp+1][p]) for pixel p
    ull acc[4][4];
    #pragma unroll
    for (int cp = 0; cp < 4; ++cp)
        #pragma unroll
        for (int p = 0; p < 4; ++p) acc[cp][p] = 0ull;

    const int cg8 = cg << 3;

    // chunk A ready (group B may still be in flight)
    cp_wait_1();
    __syncthreads();

    #pragma unroll 1
    for (int half = 0; half < 2; ++half) {
        const int cbeg = half * (CIN / 2);
        #pragma unroll 4
        for (int ci = 0; ci < CIN / 2; ++ci) {
            const int cin = cbeg + ci;
            #pragma unroll
            for (int r = 0; r < 3; ++r) {
                const float* rowp = xs + (cin * ROWS_S + ty + r) * COLS_P + XOFF + w0;
                float4 xq = *reinterpret_cast<const float4*>(rowp);   // x0..x3
                float  xm = rowp[-1];                                 // x-1
                float  xp = rowp[4];                                  // x4

                ull xd0 = dup2(xm);
                ull xd1 = dup2(xq.x);
                ull xd2 = dup2(xq.y);
                ull xd3 = dup2(xq.z);
                ull xd4 = dup2(xq.w);
                ull xd5 = dup2(xp);

                const ulonglong2* w0v =
                    reinterpret_cast<const ulonglong2*>(&ws[cin][r * 3 + 0][cg8]);
                const ulonglong2* w1v =
                    reinterpret_cast<const ulonglong2*>(&ws[cin][r * 3 + 1][cg8]);
                const ulonglong2* w2v =
                    reinterpret_cast<const ulonglong2*>(&ws[cin][r * 3 + 2][cg8]);
                ulonglong2 Wk0a = w0v[0], Wk0b = w0v[1];
                ulonglong2 Wk1a = w1v[0], Wk1b = w1v[1];
                ulonglong2 Wk2a = w2v[0], Wk2b = w2v[1];

                // per-accumulator order: kw0, kw1, kw2 (bit-exact chain)
                fma2(acc[0][0], xd0, Wk0a.x); fma2(acc[0][0], xd1, Wk1a.x); fma2(acc[0][0], xd2, Wk2a.x);
                fma2(acc[0][1], xd1, Wk0a.x); fma2(acc[0][1], xd2, Wk1a.x); fma2(acc[0][1], xd3, Wk2a.x);
                fma2(acc[0][2], xd2, Wk0a.x); fma2(acc[0][2], xd3, Wk1a.x); fma2(acc[0][2], xd4, Wk2a.x);
                fma2(acc[0][3], xd3, Wk0a.x); fma2(acc[0][3], xd4, Wk1a.x); fma2(acc[0][3], xd5, Wk2a.x);

                fma2(acc[1][0], xd0, Wk0a.y); fma2(acc[1][0], xd1, Wk1a.y); fma2(acc[1][0], xd2, Wk2a.y);
                fma2(acc[1][1], xd1, Wk0a.y); fma2(acc[1][1], xd2, Wk1a.y); fma2(acc[1][1], xd3, Wk2a.y);
                fma2(acc[1][2], xd2, Wk0a.y); fma2(acc[1][2], xd3, Wk1a.y); fma2(acc[1][2], xd4, Wk2a.y);
                fma2(acc[1][3], xd3, Wk0a.y); fma2(acc[1][3], xd4, Wk1a.y); fma2(acc[1][3], xd5, Wk2a.y);

                fma2(acc[2][0], xd0, Wk0b.x); fma2(acc[2][0], xd1, Wk1b.x); fma2(acc[2][0], xd2, Wk2b.x);
                fma2(acc[2][1], xd1, Wk0b.x); fma2(acc[2][1], xd2, Wk1b.x); fma2(acc[2][1], xd3, Wk2b.x);
                fma2(acc[2][2], xd2, Wk0b.x); fma2(acc[2][2], xd3, Wk1b.x); fma2(acc[2][2], xd4, Wk2b.x);
                fma2(acc[2][3], xd3, Wk0b.x); fma2(acc[2][3], xd4, Wk1b.x); fma2(acc[2][3], xd5, Wk2b.x);

                fma2(acc[3][0], xd0, Wk0b.y); fma2(acc[3][0], xd1, Wk1b.y); fma2(acc[3][0], xd2, Wk2b.y);
                fma2(acc[3][1], xd1, Wk0b.y); fma2(acc[3][1], xd2, Wk1b.y); fma2(acc[3][1], xd3, Wk2b.y);
                fma2(acc[3][2], xd2, Wk0b.y); fma2(acc[3][2], xd3, Wk1b.y); fma2(acc[3][2], xd4, Wk2b.y);
                fma2(acc[3][3], xd3, Wk0b.y); fma2(acc[3][3], xd4, Wk1b.y); fma2(acc[3][3], xd5, Wk2b.y);
            }
        }
        if (half == 0) {
            // chunk B ready before its first read
            cp_wait_all();
            __syncthreads();
        }
    }

    // ---- write rounded conv_t + b as float4 per cout ----
    float* o = out + (size_t)t * (COUT * HH * WWID)
                   + (size_t)c0 * (HH * WWID) + h0 * WWID + w0;
    #pragma unroll
    for (int cp = 0; cp < 4; ++cp) {
        float lo0, hi0, lo1, hi1, lo2, hi2, lo3, hi3;
        unpack2(acc[cp][0], lo0, hi0);
        unpack2(acc[cp][1], lo1, hi1);
        unpack2(acc[cp][2], lo2, hi2);
        unpack2(acc[cp][3], lo3, hi3);
        const float be = bg[c0 + 2 * cp];
        const float bo = bg[c0 + 2 * cp + 1];
        *reinterpret_cast<float4*>(o + (size_t)(2 * cp) * (HH * WWID)) =
            make_float4(fadd(lo0, be), fadd(lo1, be), fadd(lo2, be), fadd(lo3, be));
        *reinterpret_cast<float4*>(o + (size_t)(2 * cp + 1) * (HH * WWID)) =
            make_float4(fadd(hi0, bo), fadd(hi1, bo), fadd(hi2, bo), fadd(hi3, bo));
    }
}

// ---------------- K2: in-place LIF scan over t (float4, MLP=8) --------------
__global__ __launch_bounds__(64)
void scan_kernel(float* __restrict__ out)
{
    const int idx = blockIdx.x * 64 + threadIdx.x;   // float4 element index
    float4* p = reinterpret_cast<float4*>(out) + idx;
    const int stride4 = (COUT * HH * WWID) / 4;

    float4 s = make_float4(0.f, 0.f, 0.f, 0.f);
    #pragma unroll 1
    for (int tb = 0; tb < T_STEPS; tb += 8) {
        float4 c[8];
        #pragma unroll
        for (int u = 0; u < 8; ++u)
            c[u] = __ldcs(p + (size_t)(tb + u) * stride4);
        #pragma unroll
        for (int u = 0; u < 8; ++u) {
            float4 v;
            v.x = fadd(s.x, c[u].x); v.y = fadd(s.y, c[u].y);
            v.z = fadd(s.z, c[u].z); v.w = fadd(s.w, c[u].w);
            float4 k;
            k.x = (v.x >= 8.f) ? 1.f : 0.f;  k.y = (v.y >= 8.f) ? 1.f : 0.f;
            k.z = (v.z >= 8.f) ? 1.f : 0.f;  k.w = (v.w >= 8.f) ? 1.f : 0.f;
            v.x = (v.x >= 8.f) ? 0.f : v.x;  v.y = (v.y >= 8.f) ? 0.f : v.y;
            v.z = (v.z >= 8.f) ? 0.f : v.z;  v.w = (v.w >= 8.f) ? 0.f : v.w;
            s.x = fmaxf(v.x, -1.f);          s.y = fmaxf(v.y, -1.f);
            s.z = fmaxf(v.z, -1.f);          s.w = fmaxf(v.w, -1.f);
            __stcs(p + (size_t)(tb + u) * stride4, k);
        }
    }
}

extern "C" void kernel_launch(void* const* d_in, const int* in_sizes, int n_in,
                              void* d_out, int out_size)
{
    const float* x  = (const float*)d_in[0];   // [128,16,64,64]
    const float* Wg = (const float*)d_in[1];   // [64,16,3,3]
    const float* bg = (const float*)d_in[2];   // [64]
    float* out      = (float*)d_out;           // [128,64,64,64]

    static int attr_set = 0;
    size_t xs_bytes = (size_t)XS_FLOATS * sizeof(float);   // 46080 B
    if (!attr_set) {
        cudaFuncSetAttribute(conv_kernel,
                             cudaFuncAttributeMaxDynamicSharedMemorySize,
                             (int)xs_bytes);
        attr_set = 1;
    }

    dim3 grid1(8, 4, T_STEPS);
    conv_kernel<<<grid1, 256, xs_bytes>>>(x, Wg, bg, out);

    scan_kernel<<<(COUT * HH * WWID) / 4 / 64, 64>>>(out);
}